// round 1
// baseline (speedup 1.0000x reference)
#include <cuda_runtime.h>
#include <math.h>

// Problem constants (fixed shapes from reference)
#define HW     3136     // 56*56
#define HW4    784      // HW / 4 (float4 chunks per row)
#define B_SZ   64
#define C_IN   512
#define A_DIM  32
#define C_OUT  512
#define BN_EPS 1e-5f

// Scratch for pooled means: [B, C_in]
__device__ float g_pooled[B_SZ * C_IN];

// ---------------------------------------------------------------------------
// Kernel 1: global average pool. One warp per (b, c) row of 3136 floats.
// float4 loads, consecutive lanes -> consecutive 16B -> fully coalesced.
// 32768 rows / 8 warps per block = 4096 blocks.
// ---------------------------------------------------------------------------
__global__ __launch_bounds__(256) void pool_kernel(const float* __restrict__ x) {
    const int gwarp = (blockIdx.x * blockDim.x + threadIdx.x) >> 5;
    const int lane  = threadIdx.x & 31;
    if (gwarp >= B_SZ * C_IN) return;

    const float4* __restrict__ row =
        reinterpret_cast<const float4*>(x + (size_t)gwarp * HW);

    // 784 float4 per row, 32 lanes -> 24.5 iters/lane. Two independent
    // accumulators to shorten the FADD dependency chain.
    float s0 = 0.f, s1 = 0.f;
    int i = lane;
    #pragma unroll 4
    for (; i + 32 < HW4; i += 64) {
        float4 v0 = __ldg(&row[i]);
        float4 v1 = __ldg(&row[i + 32]);
        s0 += (v0.x + v0.y) + (v0.z + v0.w);
        s1 += (v1.x + v1.y) + (v1.z + v1.w);
    }
    if (i < HW4) {
        float4 v0 = __ldg(&row[i]);
        s0 += (v0.x + v0.y) + (v0.z + v0.w);
    }
    float s = s0 + s1;

    // warp reduction
    #pragma unroll
    for (int off = 16; off > 0; off >>= 1)
        s += __shfl_xor_sync(0xFFFFFFFFu, s, off);

    if (lane == 0)
        g_pooled[gwarp] = s * (1.0f / (float)HW);
}

// ---------------------------------------------------------------------------
// Kernel 2: per-batch FC chain. 64 blocks (one per b), 512 threads.
//   h[a]  = relu( BN( dot(pooled[b,:], fc_w[a,:]) ) )         (32 dots of 512)
//   ch[c] = sigmoid( dot(h, channel_fc_w[c,:]) + ch_b[c] )    (512 dots of 32)
//   f[o]  = sigmoid( dot(h, filter_fc_w[o,:]) + f_b[o] )      (512 dots of 32)
// Output layout: d_out[0 : B*C_in] = ch_att, d_out[B*C_in : ] = f_att.
// ---------------------------------------------------------------------------
__global__ __launch_bounds__(512) void fc_kernel(
    const float* __restrict__ fc_w,         // [A, C_in]
    const float* __restrict__ bn_gamma,     // [A]
    const float* __restrict__ bn_beta,      // [A]
    const float* __restrict__ bn_mean,      // [A]
    const float* __restrict__ bn_var,       // [A]
    const float* __restrict__ channel_fc_w, // [C_in, A]
    const float* __restrict__ channel_fc_b, // [C_in]
    const float* __restrict__ filter_fc_w,  // [C_out, A]
    const float* __restrict__ filter_fc_b,  // [C_out]
    float* __restrict__ out)                // [2 * B * 512]
{
    __shared__ float s_pooled[C_IN];
    __shared__ float s_h[A_DIM];

    const int b   = blockIdx.x;
    const int tid = threadIdx.x;

    // stage pooled row into smem
    s_pooled[tid] = g_pooled[b * C_IN + tid];
    __syncthreads();

    // h: threads 0..31 each own one attention channel a
    if (tid < A_DIM) {
        const float* __restrict__ w = fc_w + tid * C_IN;
        float acc = 0.f;
        #pragma unroll 8
        for (int c = 0; c < C_IN; ++c)
            acc = fmaf(s_pooled[c], w[c], acc);  // smem broadcast reads

        // BatchNorm (eval) + ReLU
        float inv_std = rsqrtf(bn_var[tid] + BN_EPS);
        float hv = (acc - bn_mean[tid]) * (bn_gamma[tid] * inv_std) + bn_beta[tid];
        s_h[tid] = fmaxf(hv, 0.f);
    }
    __syncthreads();

    // channel attention: thread c
    {
        const float* __restrict__ w = channel_fc_w + tid * A_DIM;
        float acc = channel_fc_b[tid];
        #pragma unroll
        for (int a = 0; a < A_DIM; ++a)
            acc = fmaf(s_h[a], w[a], acc);
        out[b * C_IN + tid] = 1.0f / (1.0f + expf(-acc));
    }

    // filter attention: thread o
    {
        const float* __restrict__ w = filter_fc_w + tid * A_DIM;
        float acc = filter_fc_b[tid];
        #pragma unroll
        for (int a = 0; a < A_DIM; ++a)
            acc = fmaf(s_h[a], w[a], acc);
        out[(size_t)B_SZ * C_IN + b * C_OUT + tid] = 1.0f / (1.0f + expf(-acc));
    }
}

extern "C" void kernel_launch(void* const* d_in, const int* in_sizes, int n_in,
                              void* d_out, int out_size) {
    const float* x            = (const float*)d_in[0];
    const float* fc_w         = (const float*)d_in[1];
    const float* bn_gamma     = (const float*)d_in[2];
    const float* bn_beta      = (const float*)d_in[3];
    const float* bn_mean      = (const float*)d_in[4];
    const float* bn_var       = (const float*)d_in[5];
    const float* channel_fc_w = (const float*)d_in[6];
    const float* channel_fc_b = (const float*)d_in[7];
    const float* filter_fc_w  = (const float*)d_in[8];
    const float* filter_fc_b  = (const float*)d_in[9];
    float* out = (float*)d_out;

    // Kernel 1: 32768 rows, 8 warps/block -> 4096 blocks
    pool_kernel<<<(B_SZ * C_IN) / 8, 256>>>(x);

    // Kernel 2: one block per batch element
    fc_kernel<<<B_SZ, 512>>>(fc_w, bn_gamma, bn_beta, bn_mean, bn_var,
                             channel_fc_w, channel_fc_b,
                             filter_fc_w, filter_fc_b, out);
}

// round 2
// speedup vs baseline: 1.5192x; 1.5192x over previous
#include <cuda_runtime.h>
#include <math.h>

// Problem constants (fixed shapes from reference)
#define HW     3136     // 56*56
#define HW4    784      // HW / 4 (float4 chunks per row)
#define B_SZ   64
#define C_IN   512
#define A_DIM  32
#define C_OUT  512
#define BN_EPS 1e-5f

// Scratch for pooled means: [B, C_in]
__device__ float g_pooled[B_SZ * C_IN];

// ---------------------------------------------------------------------------
// Kernel 1: global average pool. One warp per (b, c) row of 3136 floats.
// float4 loads, consecutive lanes -> consecutive 16B -> fully coalesced.
// 32768 rows / 8 warps per block = 4096 blocks. (~60us, ~85% of HBM floor)
// ---------------------------------------------------------------------------
__global__ __launch_bounds__(256) void pool_kernel(const float* __restrict__ x) {
    const int gwarp = (blockIdx.x * blockDim.x + threadIdx.x) >> 5;
    const int lane  = threadIdx.x & 31;
    if (gwarp >= B_SZ * C_IN) return;

    const float4* __restrict__ row =
        reinterpret_cast<const float4*>(x + (size_t)gwarp * HW);

    float s0 = 0.f, s1 = 0.f;
    int i = lane;
    #pragma unroll 4
    for (; i + 32 < HW4; i += 64) {
        float4 v0 = __ldg(&row[i]);
        float4 v1 = __ldg(&row[i + 32]);
        s0 += (v0.x + v0.y) + (v0.z + v0.w);
        s1 += (v1.x + v1.y) + (v1.z + v1.w);
    }
    if (i < HW4) {
        float4 v0 = __ldg(&row[i]);
        s0 += (v0.x + v0.y) + (v0.z + v0.w);
    }
    float s = s0 + s1;

    #pragma unroll
    for (int off = 16; off > 0; off >>= 1)
        s += __shfl_xor_sync(0xFFFFFFFFu, s, off);

    if (lane == 0)
        g_pooled[gwarp] = s * (1.0f / (float)HW);
}

// ---------------------------------------------------------------------------
// Kernel 2: per-batch FC chain. 64 blocks (one per b), 512 threads.
// Phase 1 (h): warp w computes a = {w, w+16} as warp-parallel dot products.
//   Each lane: 4 coalesced float4 loads of fc_w row + smem float4 of pooled,
//   16 FMAs, then shuffle reduce. Replaces the old serial 512-FMA chain.
// Phase 2: each thread computes one channel-att and one filter-att output,
//   float4-vectorized weight rows (128B aligned), sigmoid.
// ---------------------------------------------------------------------------
__global__ __launch_bounds__(512) void fc_kernel(
    const float* __restrict__ fc_w,         // [A, C_in]
    const float* __restrict__ bn_gamma,     // [A]
    const float* __restrict__ bn_beta,      // [A]
    const float* __restrict__ bn_mean,      // [A]
    const float* __restrict__ bn_var,       // [A]
    const float* __restrict__ channel_fc_w, // [C_in, A]
    const float* __restrict__ channel_fc_b, // [C_in]
    const float* __restrict__ filter_fc_w,  // [C_out, A]
    const float* __restrict__ filter_fc_b,  // [C_out]
    float* __restrict__ out)                // [2 * B * 512]
{
    __shared__ float4 s_pooled4[C_IN / 4];  // 128 float4
    __shared__ float  s_h[A_DIM];

    const int b    = blockIdx.x;
    const int tid  = threadIdx.x;
    const int warp = tid >> 5;
    const int lane = tid & 31;

    // stage pooled row into smem (threads 0..127, float4)
    if (tid < C_IN / 4)
        s_pooled4[tid] = reinterpret_cast<const float4*>(g_pooled + b * C_IN)[tid];
    __syncthreads();

    // Phase 1: h[a] for a = warp and a = warp+16
    #pragma unroll
    for (int k = 0; k < 2; ++k) {
        const int a = warp + k * 16;
        const float4* __restrict__ w4 =
            reinterpret_cast<const float4*>(fc_w + a * C_IN);
        float acc = 0.f;
        #pragma unroll
        for (int j = 0; j < 4; ++j) {
            float4 wv = __ldg(&w4[lane + 32 * j]);
            float4 pv = s_pooled4[lane + 32 * j];
            acc = fmaf(wv.x, pv.x, acc);
            acc = fmaf(wv.y, pv.y, acc);
            acc = fmaf(wv.z, pv.z, acc);
            acc = fmaf(wv.w, pv.w, acc);
        }
        #pragma unroll
        for (int off = 16; off > 0; off >>= 1)
            acc += __shfl_xor_sync(0xFFFFFFFFu, acc, off);

        if (lane == 0) {
            float inv_std = rsqrtf(bn_var[a] + BN_EPS);
            float hv = (acc - bn_mean[a]) * (bn_gamma[a] * inv_std) + bn_beta[a];
            s_h[a] = fmaxf(hv, 0.f);
        }
    }
    __syncthreads();

    // Phase 2a: channel attention, thread = channel c (row is 128B aligned)
    {
        const float4* __restrict__ w4 =
            reinterpret_cast<const float4*>(channel_fc_w + tid * A_DIM);
        float acc = channel_fc_b[tid];
        #pragma unroll
        for (int j = 0; j < 8; ++j) {
            float4 wv = __ldg(&w4[j]);
            acc = fmaf(s_h[4 * j + 0], wv.x, acc);
            acc = fmaf(s_h[4 * j + 1], wv.y, acc);
            acc = fmaf(s_h[4 * j + 2], wv.z, acc);
            acc = fmaf(s_h[4 * j + 3], wv.w, acc);
        }
        out[b * C_IN + tid] = 1.0f / (1.0f + expf(-acc));
    }

    // Phase 2b: filter attention, thread = output filter o
    {
        const float4* __restrict__ w4 =
            reinterpret_cast<const float4*>(filter_fc_w + tid * A_DIM);
        float acc = filter_fc_b[tid];
        #pragma unroll
        for (int j = 0; j < 8; ++j) {
            float4 wv = __ldg(&w4[j]);
            acc = fmaf(s_h[4 * j + 0], wv.x, acc);
            acc = fmaf(s_h[4 * j + 1], wv.y, acc);
            acc = fmaf(s_h[4 * j + 2], wv.z, acc);
            acc = fmaf(s_h[4 * j + 3], wv.w, acc);
        }
        out[(size_t)B_SZ * C_IN + b * C_OUT + tid] = 1.0f / (1.0f + expf(-acc));
    }
}

extern "C" void kernel_launch(void* const* d_in, const int* in_sizes, int n_in,
                              void* d_out, int out_size) {
    const float* x            = (const float*)d_in[0];
    const float* fc_w         = (const float*)d_in[1];
    const float* bn_gamma     = (const float*)d_in[2];
    const float* bn_beta      = (const float*)d_in[3];
    const float* bn_mean      = (const float*)d_in[4];
    const float* bn_var       = (const float*)d_in[5];
    const float* channel_fc_w = (const float*)d_in[6];
    const float* channel_fc_b = (const float*)d_in[7];
    const float* filter_fc_w  = (const float*)d_in[8];
    const float* filter_fc_b  = (const float*)d_in[9];
    float* out = (float*)d_out;

    pool_kernel<<<(B_SZ * C_IN) / 8, 256>>>(x);

    fc_kernel<<<B_SZ, 512>>>(fc_w, bn_gamma, bn_beta, bn_mean, bn_var,
                             channel_fc_w, channel_fc_b,
                             filter_fc_w, filter_fc_b, out);
}